// round 16
// baseline (speedup 1.0000x reference)
#include <cuda_runtime.h>
#include <cuda_fp16.h>
#include <math.h>
#include <stdint.h>

#define NB 2
#define NM 2048
#define ND 1024
#define NH 16
#define NHD 64
#define NTOK (NB*NM)   // 4096
#define GRID_P 296     // persistent grid: 148 SMs x 2 CTAs

// ---- fp16 scratch (static device globals: allocation-free) ----
__device__ __half h_x [NTOK*ND];
__device__ __half h_wq[ND*ND];
__device__ __half h_wk[ND*ND];
__device__ __half h_wv[ND*ND];
__device__ __half h_ipw[3*ND*ND];
__device__ __half h_ow[ND*ND];
__device__ __half h_q [NTOK*ND];
__device__ __half h_k [NTOK*ND];
__device__ __half h_v [NTOK*ND];
__device__ __half h_qh[NTOK*ND];
__device__ __half h_kh[NTOK*ND];
__device__ __half h_vh[NTOK*ND];
__device__ __half h_o [NTOK*ND];
__device__ float  g_theta[ND/2];

__global__ void init_theta_kernel() {
    int p = threadIdx.x;
    if (p < ND/2) {
        double e = -2.0 * ((double)p - 1.0) / (double)ND;
        g_theta[p] = (float)exp(e * log(10000.0));
    }
}

// ---- fused fp32 -> fp16 convert over 6 segments ----
struct CvtArgs {
    const float* src[6];
    __half*      dst[6];
    int          cum8[7];
};
__global__ void f2h_multi(CvtArgs a) {
    int i = blockIdx.x * blockDim.x + threadIdx.x;
    if (i >= a.cum8[6]) return;
    int s = 0;
#pragma unroll
    for (int t = 1; t < 6; t++) if (i >= a.cum8[t]) s = t;
    int j = i - a.cum8[s];
    const float4* in = (const float4*)a.src[s];
    uint2* out = (uint2*)a.dst[s];
    float4 x = in[2*j], y = in[2*j+1];
    __half2 h0 = __floats2half2_rn(x.x, x.y);
    __half2 h1 = __floats2half2_rn(x.z, x.w);
    __half2 h2 = __floats2half2_rn(y.x, y.y);
    __half2 h3 = __floats2half2_rn(y.z, y.w);
    out[2*j]   = make_uint2(*(uint32_t*)&h0, *(uint32_t*)&h1);
    out[2*j+1] = make_uint2(*(uint32_t*)&h2, *(uint32_t*)&h3);
}

// ---------------------------------------------------------------------------
// helpers
// ---------------------------------------------------------------------------
__device__ __forceinline__ uint32_t sptr(const void* p) {
    return (uint32_t)__cvta_generic_to_shared(p);
}
__device__ __forceinline__ void ldsm_x4(uint32_t* r, uint32_t a) {
    asm volatile("ldmatrix.sync.aligned.m8n8.x4.shared.b16 {%0,%1,%2,%3}, [%4];"
        : "=r"(r[0]), "=r"(r[1]), "=r"(r[2]), "=r"(r[3]) : "r"(a));
}
__device__ __forceinline__ void ldsm_x4t(uint32_t* r, uint32_t a) {
    asm volatile("ldmatrix.sync.aligned.m8n8.x4.trans.shared.b16 {%0,%1,%2,%3}, [%4];"
        : "=r"(r[0]), "=r"(r[1]), "=r"(r[2]), "=r"(r[3]) : "r"(a));
}
__device__ __forceinline__ void mma_f16(float* d, const uint32_t* a, uint32_t b0, uint32_t b1) {
    asm volatile(
        "mma.sync.aligned.m16n8k16.row.col.f32.f16.f16.f32 "
        "{%0,%1,%2,%3}, {%4,%5,%6,%7}, {%8,%9}, {%0,%1,%2,%3};"
        : "+f"(d[0]), "+f"(d[1]), "+f"(d[2]), "+f"(d[3])
        : "r"(a[0]), "r"(a[1]), "r"(a[2]), "r"(a[3]), "r"(b0), "r"(b1));
}
__device__ __forceinline__ void cp_async16(void* smem, const void* gmem) {
    asm volatile("cp.async.cg.shared.global [%0], [%1], 16;" :: "r"(sptr(smem)), "l"(gmem));
}
__device__ __forceinline__ void cp_commit() { asm volatile("cp.async.commit_group;"); }
template<int N> __device__ __forceinline__ void cp_wait() {
    asm volatile("cp.async.wait_group %0;" :: "n"(N));
}
__device__ __forceinline__ uint32_t packh2(float a, float b) {
    __half2 h = __floats2half2_rn(a, b);
    return *(uint32_t*)&h;
}

#define GLD 72          // padded smem row stride (halves)
#define NKB 16          // 1024 / 64

struct GemmPtrs {
    const __half* A[3];
    const __half* W[3];
    const float*  bias[3];
    __half*       Ch[3];
    float*        Cf;
    float         scale[3];
    int           ntiles;   // total 128x128 tiles (sel-major)
};

// ===========================================================================
// GEMM variant A (RoPE epilogue): persistent, 256 threads, 8 warps
// (64x32 tiles), BK=64, 2-stage. __launch_bounds__(256,2).
// ===========================================================================
#define SMEM_G256 (4*128*GLD*2)   // 73728 bytes

__global__ __launch_bounds__(256, 2) void gemm_rope_kernel(GemmPtrs P)
{
    extern __shared__ __half smh[];
    __half* As = smh;                    // [2][128*GLD]
    __half* Bs = smh + 2 * 128 * GLD;

    const int tid  = threadIdx.x;
    const int lane = tid & 31, warp = tid >> 5;
    const int g = lane >> 2, tig = lane & 3;
    const int wm = (warp & 1) * 64, wn = (warp >> 1) * 32;

    const int lrow = tid >> 3;
    const int lch  = (tid & 7) * 8;
    const int a_row = lane & 15;
    const int a_col = (lane & 16) >> 1;

    for (int tile = blockIdx.x; tile < P.ntiles; tile += gridDim.x) {
        const int sel = tile >> 8;
        const int m0 = ((tile >> 3) & 31) << 7;
        const int n0 = (tile & 7) << 7;
        const __half* A = P.A[sel];
        const __half* W = P.W[sel];

        float acc[4][4][4];
#pragma unroll
        for (int mf = 0; mf < 4; mf++)
#pragma unroll
            for (int nf = 0; nf < 4; nf++)
#pragma unroll
                for (int t = 0; t < 4; t++) acc[mf][nf][t] = 0.f;

        auto issue = [&](int kb, int buf) {
            const __half* Ab = A + (size_t)m0 * ND + kb * 64 + lch;
            const __half* Wb = W + (size_t)n0 * ND + kb * 64 + lch;
            __half* Asb = As + buf * 128 * GLD;
            __half* Bsb = Bs + buf * 128 * GLD;
#pragma unroll
            for (int i = 0; i < 4; i++) {
                int r = lrow + i * 32;
                cp_async16(Asb + r * GLD + lch, Ab + (size_t)r * ND);
                cp_async16(Bsb + r * GLD + lch, Wb + (size_t)r * ND);
            }
        };

        issue(0, 0); cp_commit();
        int buf = 0;
#pragma unroll 1
        for (int kb = 0; kb < NKB; kb++) {
            if (kb + 1 < NKB) { issue(kb + 1, buf ^ 1); cp_commit(); cp_wait<1>(); }
            else              { cp_wait<0>(); }
            __syncthreads();

            const __half* Asb = As + buf * 128 * GLD;
            const __half* Bsb = Bs + buf * 128 * GLD;
#pragma unroll
            for (int s = 0; s < 4; s++) {
                uint32_t af[4][4];
#pragma unroll
                for (int mf = 0; mf < 4; mf++)
                    ldsm_x4(af[mf], sptr(Asb + (wm + mf * 16 + a_row) * GLD + s * 16 + a_col));
                uint32_t bf[2][4];
#pragma unroll
                for (int np = 0; np < 2; np++) {
                    int row = wn + np * 16 + (lane & 7) + ((lane & 16) >> 1);
                    int col = s * 16 + (lane & 8);
                    ldsm_x4(bf[np], sptr(Bsb + row * GLD + col));
                }
#pragma unroll
                for (int mf = 0; mf < 4; mf++)
#pragma unroll
                    for (int np = 0; np < 2; np++) {
                        mma_f16(acc[mf][np * 2],     af[mf], bf[np][0], bf[np][1]);
                        mma_f16(acc[mf][np * 2 + 1], af[mf], bf[np][2], bf[np][3]);
                    }
            }
            __syncthreads();
            buf ^= 1;
        }

        // RoPE epilogue (sincosf; c0/c1 = even/odd pair)
        __half* Ch = P.Ch[sel];
#pragma unroll
        for (int nf = 0; nf < 4; nf++) {
            int col = n0 + wn + nf * 8 + 2 * tig;
            float th = g_theta[col >> 1];
#pragma unroll
            for (int mf = 0; mf < 4; mf++) {
                int r0 = m0 + wm + mf * 16 + g;
#pragma unroll
                for (int hlf = 0; hlf < 2; hlf++) {
                    int r = r0 + hlf * 8;
                    float sn, cn;
                    sincosf((float)(r & (NM - 1)) * th, &sn, &cn);
                    float xe = acc[mf][nf][2 * hlf], xo = acc[mf][nf][2 * hlf + 1];
                    *(__half2*)(Ch + (size_t)r * ND + col) =
                        __floats2half2_rn(xe * cn + xo * sn, -xe * sn + xo * cn);
                }
            }
        }
        __syncthreads();   // smem safe before next tile's prologue
    }
}

// ===========================================================================
// GEMM variant B (bias epilogues): persistent, 128 threads, 4 warps
// (64x64 tiles), BK=64, 3-stage, one sync/iter, fragment double-buffering.
// __launch_bounds__(128,2). EPI: 1 = (+bias)*scale -> fp16, 3 = +bias -> fp32.
// ===========================================================================
#define NSTG 3
#define STG_H (128*GLD)
#define SMEM_G128 (NSTG * 2 * STG_H * 2)   // 110592 bytes

template<int EPI>
__global__ __launch_bounds__(128, 2) void gemm_bias_kernel(GemmPtrs P)
{
    extern __shared__ __half smh[];
    const int tid  = threadIdx.x;
    const int lane = tid & 31, warp = tid >> 5;
    const int g = lane >> 2, tig = lane & 3;
    const int wm = (warp & 1) * 64, wn = (warp >> 1) * 64;

    const int lrow = tid >> 3;           // 0..15
    const int lch  = (tid & 7) * 8;
    const int a_row = lane & 15;
    const int a_col = (lane & 16) >> 1;
    const int b_rsel = (lane & 7) + ((lane & 16) >> 1);
    const int b_csel = lane & 8;

    for (int tile = blockIdx.x; tile < P.ntiles; tile += gridDim.x) {
        const int sel = tile >> 8;
        const int m0 = ((tile >> 3) & 31) << 7;
        const int n0 = (tile & 7) << 7;
        const __half* A = P.A[sel];
        const __half* W = P.W[sel];

        float acc[4][8][4];
#pragma unroll
        for (int mf = 0; mf < 4; mf++)
#pragma unroll
            for (int nf = 0; nf < 8; nf++)
#pragma unroll
                for (int t = 0; t < 4; t++) acc[mf][nf][t] = 0.f;

        auto issue = [&](int kb, int stg) {
            __half* Asb = smh + stg * 2 * STG_H;
            __half* Bsb = Asb + STG_H;
            const __half* Ap = A + (size_t)m0 * ND + kb * 64 + lch;
            const __half* Wp = W + (size_t)n0 * ND + kb * 64 + lch;
#pragma unroll
            for (int i = 0; i < 8; i++) {
                int r = lrow + i * 16;
                cp_async16(Asb + r * GLD + lch, Ap + (size_t)r * ND);
                cp_async16(Bsb + r * GLD + lch, Wp + (size_t)r * ND);
            }
        };

        issue(0, 0); cp_commit();
        issue(1, 1); cp_commit();

#pragma unroll 1
        for (int kb = 0; kb < NKB; kb++) {
            cp_wait<1>();
            __syncthreads();
            if (kb + 2 < NKB) issue(kb + 2, (kb + 2) % 3);
            cp_commit();

            const int stg = kb % 3;
            const __half* Asb = smh + stg * 2 * STG_H;
            const __half* Bsb = Asb + STG_H;

            uint32_t af[2][4][4], bf[2][4][4];
#pragma unroll
            for (int mf = 0; mf < 4; mf++)
                ldsm_x4(af[0][mf], sptr(Asb + (wm + mf * 16 + a_row) * GLD + a_col));
#pragma unroll
            for (int np = 0; np < 4; np++)
                ldsm_x4(bf[0][np], sptr(Bsb + (wn + np * 16 + b_rsel) * GLD + b_csel));

#pragma unroll
            for (int s = 0; s < 4; s++) {
                const int cur = s & 1, nxt = cur ^ 1;
                if (s < 3) {
#pragma unroll
                    for (int mf = 0; mf < 4; mf++)
                        ldsm_x4(af[nxt][mf],
                            sptr(Asb + (wm + mf * 16 + a_row) * GLD + (s + 1) * 16 + a_col));
#pragma unroll
                    for (int np = 0; np < 4; np++)
                        ldsm_x4(bf[nxt][np],
                            sptr(Bsb + (wn + np * 16 + b_rsel) * GLD + (s + 1) * 16 + b_csel));
                }
#pragma unroll
                for (int mf = 0; mf < 4; mf++)
#pragma unroll
                    for (int np = 0; np < 4; np++) {
                        mma_f16(acc[mf][np * 2],     af[cur][mf], bf[cur][np][0], bf[cur][np][1]);
                        mma_f16(acc[mf][np * 2 + 1], af[cur][mf], bf[cur][np][2], bf[cur][np][3]);
                    }
            }
        }

        if (EPI == 1) {
            float sc = P.scale[sel];
            __half* Ch = P.Ch[sel];
#pragma unroll
            for (int nf = 0; nf < 8; nf++) {
                int col = n0 + wn + nf * 8 + 2 * tig;
                float2 bv = *(const float2*)(P.bias[sel] + col);
#pragma unroll
                for (int mf = 0; mf < 4; mf++) {
                    int r0 = m0 + wm + mf * 16 + g;
                    *(__half2*)(Ch + (size_t)r0 * ND + col) =
                        __floats2half2_rn((acc[mf][nf][0] + bv.x) * sc,
                                          (acc[mf][nf][1] + bv.y) * sc);
                    *(__half2*)(Ch + (size_t)(r0 + 8) * ND + col) =
                        __floats2half2_rn((acc[mf][nf][2] + bv.x) * sc,
                                          (acc[mf][nf][3] + bv.y) * sc);
                }
            }
        } else {
            float* Cf = P.Cf;
#pragma unroll
            for (int nf = 0; nf < 8; nf++) {
                int col = n0 + wn + nf * 8 + 2 * tig;
                float2 bv = *(const float2*)(P.bias[sel] + col);
#pragma unroll
                for (int mf = 0; mf < 4; mf++) {
                    int r0 = m0 + wm + mf * 16 + g;
                    float2 v0 = { acc[mf][nf][0] + bv.x, acc[mf][nf][1] + bv.y };
                    float2 v1 = { acc[mf][nf][2] + bv.x, acc[mf][nf][3] + bv.y };
                    *(float2*)(Cf + (size_t)r0 * ND + col)       = v0;
                    *(float2*)(Cf + (size_t)(r0 + 8) * ND + col) = v1;
                }
            }
        }
        __syncthreads();   // smem safe before next tile's prologue
    }
}

// ===========================================================================
// Causal flash attention, fp16 mma.sync. Block = (64-q tile, h, b), 128 thr.
// 4 warps x 16 q rows; P fed into P.V MMA directly from S registers.
// K/V double-buffered via cp.async. (1/sqrt(hd))*log2(e) pre-folded into qh,
// so softmax uses exp2f. __launch_bounds__(128,4).  [round-6/13 config]
// ===========================================================================
#define ATD 72
#define AKOFF (64*ATD)
#define AVOFF (AKOFF + 2*64*ATD)
#define ASM_TOT ((64 + 2*64 + 2*64) * ATD * 2)   // 46080 bytes

__global__ __launch_bounds__(128, 4) void attn_f16_kernel(
    const __half* __restrict__ qh, const __half* __restrict__ kh,
    const __half* __restrict__ vh, __half* __restrict__ o)
{
    extern __shared__ __half sm[];
    __half* Qs = sm;
    __half* Ks = sm + AKOFF;
    __half* Vs = sm + AVOFF;

    const int tid  = threadIdx.x;
    const int lane = tid & 31, warp = tid >> 5;
    const int g = lane >> 2, tig = lane & 3;
    const int qi = (int)gridDim.x - 1 - (int)blockIdx.x;   // longest first
    const int h = blockIdx.y, b = blockIdx.z;
    const int q0 = qi * 64;

    const __half* qb = qh + (size_t)b * NM * ND + h * NHD;
    const __half* kb = kh + (size_t)b * NM * ND + h * NHD;
    const __half* vb = vh + (size_t)b * NM * ND + h * NHD;

    const int lrow = tid >> 3;       // 0..15
    const int lch  = (tid & 7) * 8;

#pragma unroll
    for (int i = 0; i < 4; i++) {
        int r = lrow + i * 16;
        cp_async16(Qs + r * ATD + lch, qb + (size_t)(q0 + r) * ND + lch);
    }

    auto issue_kv = [&](int kt, int bufb) {
        int k0 = kt * 64;
        __half* Kd = Ks + bufb * 64 * ATD;
        __half* Vd = Vs + bufb * 64 * ATD;
#pragma unroll
        for (int i = 0; i < 4; i++) {
            int r = lrow + i * 16;
            cp_async16(Kd + r * ATD + lch, kb + (size_t)(k0 + r) * ND + lch);
            cp_async16(Vd + r * ATD + lch, vb + (size_t)(k0 + r) * ND + lch);
        }
    };

    float m_i[2] = { -INFINITY, -INFINITY };
    float l_i[2] = { 0.f, 0.f };
    float Oa[8][4];
#pragma unroll
    for (int nf = 0; nf < 8; nf++)
#pragma unroll
        for (int t = 0; t < 4; t++) Oa[nf][t] = 0.f;

    issue_kv(0, 0); cp_commit();
    int buf = 0;

    const int a_row = lane & 15;
    const int a_col = (lane & 16) >> 1;

    for (int kt = 0; kt <= qi; kt++) {
        if (kt < qi) { issue_kv(kt + 1, buf ^ 1); cp_commit(); cp_wait<1>(); }
        else         { cp_wait<0>(); }
        __syncthreads();

        const __half* Kb = Ks + buf * 64 * ATD;
        const __half* Vb = Vs + buf * 64 * ATD;

        float S[8][4];
#pragma unroll
        for (int nf = 0; nf < 8; nf++)
#pragma unroll
            for (int t = 0; t < 4; t++) S[nf][t] = 0.f;

#pragma unroll
        for (int s = 0; s < 4; s++) {
            uint32_t af[4];
            ldsm_x4(af, sptr(Qs + (warp * 16 + a_row) * ATD + s * 16 + a_col));
#pragma unroll
            for (int np = 0; np < 4; np++) {
                uint32_t bf[4];
                int row = np * 16 + (lane & 7) + ((lane & 16) >> 1);
                int col = s * 16 + (lane & 8);
                ldsm_x4(bf, sptr(Kb + row * ATD + col));
                mma_f16(S[np * 2],     af, bf[0], bf[1]);
                mma_f16(S[np * 2 + 1], af, bf[2], bf[3]);
            }
        }

        if (kt == qi) {
            const int r0 = warp * 16 + g, r1 = r0 + 8;
#pragma unroll
            for (int nf = 0; nf < 8; nf++) {
                int c = nf * 8 + 2 * tig;
                if (c     > r0) S[nf][0] = -INFINITY;
                if (c + 1 > r0) S[nf][1] = -INFINITY;
                if (c     > r1) S[nf][2] = -INFINITY;
                if (c + 1 > r1) S[nf][3] = -INFINITY;
            }
        }

#pragma unroll
        for (int r = 0; r < 2; r++) {
            float mx = -INFINITY;
#pragma unroll
            for (int nf = 0; nf < 8; nf++)
                mx = fmaxf(mx, fmaxf(S[nf][2 * r], S[nf][2 * r + 1]));
            mx = fmaxf(mx, __shfl_xor_sync(0xffffffffu, mx, 1));
            mx = fmaxf(mx, __shfl_xor_sync(0xffffffffu, mx, 2));
            float mn = fmaxf(m_i[r], mx);
            float alpha = exp2f(m_i[r] - mn);
            float rs = 0.f;
#pragma unroll
            for (int nf = 0; nf < 8; nf++) {
                float p0 = exp2f(S[nf][2 * r] - mn);
                float p1 = exp2f(S[nf][2 * r + 1] - mn);
                S[nf][2 * r] = p0; S[nf][2 * r + 1] = p1;
                rs += p0 + p1;
            }
            rs += __shfl_xor_sync(0xffffffffu, rs, 1);
            rs += __shfl_xor_sync(0xffffffffu, rs, 2);
            l_i[r] = l_i[r] * alpha + rs;
            m_i[r] = mn;
#pragma unroll
            for (int nf = 0; nf < 8; nf++) {
                Oa[nf][2 * r]     *= alpha;
                Oa[nf][2 * r + 1] *= alpha;
            }
        }

#pragma unroll
        for (int s = 0; s < 4; s++) {
            uint32_t af[4];
            af[0] = packh2(S[2 * s][0],     S[2 * s][1]);
            af[1] = packh2(S[2 * s][2],     S[2 * s][3]);
            af[2] = packh2(S[2 * s + 1][0], S[2 * s + 1][1]);
            af[3] = packh2(S[2 * s + 1][2], S[2 * s + 1][3]);
#pragma unroll
            for (int np = 0; np < 4; np++) {
                uint32_t bf[4];
                int row = s * 16 + (lane & 7) + (lane & 8);
                int col = np * 16 + ((lane & 16) >> 1);
                ldsm_x4t(bf, sptr(Vb + row * ATD + col));
                mma_f16(Oa[np * 2],     af, bf[0], bf[1]);
                mma_f16(Oa[np * 2 + 1], af, bf[2], bf[3]);
            }
        }
        __syncthreads();
        buf ^= 1;
    }

    __half* ob = o + (size_t)b * NM * ND + h * NHD;
#pragma unroll
    for (int r = 0; r < 2; r++) {
        float inv = 1.f / l_i[r];
        int row = q0 + warp * 16 + g + r * 8;
#pragma unroll
        for (int nf = 0; nf < 8; nf++)
            *(__half2*)(ob + (size_t)row * ND + nf * 8 + 2 * tig) =
                __floats2half2_rn(Oa[nf][2 * r] * inv, Oa[nf][2 * r + 1] * inv);
    }
}

// ===========================================================================
extern "C" void kernel_launch(void* const* d_in, const int* in_sizes, int n_in,
                              void* d_out, int out_size)
{
    const float* x   = (const float*)d_in[0];
    const float* wq  = (const float*)d_in[1];
    const float* wk  = (const float*)d_in[2];
    const float* wv  = (const float*)d_in[3];
    const float* ipw = (const float*)d_in[4];
    const float* ipb = (const float*)d_in[5];
    const float* ow  = (const float*)d_in[6];
    const float* ob  = (const float*)d_in[7];
    float* out = (float*)d_out;

    __half *hx, *hwq, *hwk, *hwv, *hipw, *how, *hq, *hk, *hv, *hqh, *hkh, *hvh, *ho;
    cudaGetSymbolAddress((void**)&hx,  h_x);
    cudaGetSymbolAddress((void**)&hwq, h_wq);
    cudaGetSymbolAddress((void**)&hwk, h_wk);
    cudaGetSymbolAddress((void**)&hwv, h_wv);
    cudaGetSymbolAddress((void**)&hipw, h_ipw);
    cudaGetSymbolAddress((void**)&how, h_ow);
    cudaGetSymbolAddress((void**)&hq,  h_q);
    cudaGetSymbolAddress((void**)&hk,  h_k);
    cudaGetSymbolAddress((void**)&hv,  h_v);
    cudaGetSymbolAddress((void**)&hqh, h_qh);
    cudaGetSymbolAddress((void**)&hkh, h_kh);
    cudaGetSymbolAddress((void**)&hvh, h_vh);
    cudaGetSymbolAddress((void**)&ho,  h_o);

    cudaFuncSetAttribute(gemm_rope_kernel,
                         cudaFuncAttributeMaxDynamicSharedMemorySize, SMEM_G256);
    cudaFuncSetAttribute(gemm_bias_kernel<1>,
                         cudaFuncAttributeMaxDynamicSharedMemorySize, SMEM_G128);
    cudaFuncSetAttribute(gemm_bias_kernel<3>,
                         cudaFuncAttributeMaxDynamicSharedMemorySize, SMEM_G128);
    cudaFuncSetAttribute(attn_f16_kernel,
                         cudaFuncAttributeMaxDynamicSharedMemorySize, ASM_TOT);

    init_theta_kernel<<<1, 512>>>();

    // fused converts
    {
        CvtArgs a{};
        const float* srcs[6] = { x, wq, wk, wv, ipw, ow };
        __half* dsts[6] = { hx, hwq, hwk, hwv, hipw, how };
        int sizes[6] = { NTOK*ND, ND*ND, ND*ND, ND*ND, 3*ND*ND, ND*ND };
        int cum = 0;
        for (int i = 0; i < 6; i++) {
            a.src[i] = srcs[i]; a.dst[i] = dsts[i];
            a.cum8[i] = cum; cum += sizes[i] / 8;
        }
        a.cum8[6] = cum;
        f2h_multi<<<(cum + 255) / 256, 256>>>(a);
    }

    // QKV projections with fused RoPE epilogue (fp16 out), persistent grid
    {
        GemmPtrs P{};
        P.A[0] = hx; P.A[1] = hx; P.A[2] = hx;
        P.W[0] = hwq; P.W[1] = hwk; P.W[2] = hwv;
        P.Ch[0] = hq; P.Ch[1] = hk; P.Ch[2] = hv;
        P.ntiles = 3 * 256;
        gemm_rope_kernel<<<GRID_P, 256, SMEM_G256>>>(P);
    }
    // in_proj (bias fused; qh scaled by 0.125*log2e), persistent grid
    {
        GemmPtrs P{};
        P.A[0] = hq; P.A[1] = hk; P.A[2] = hv;
        P.W[0] = hipw; P.W[1] = hipw + ND * ND; P.W[2] = hipw + 2 * ND * ND;
        P.bias[0] = ipb; P.bias[1] = ipb + ND; P.bias[2] = ipb + 2 * ND;
        P.Ch[0] = hqh; P.Ch[1] = hkh; P.Ch[2] = hvh;
        P.scale[0] = 0.125f * 1.44269504088896341f; P.scale[1] = 1.f; P.scale[2] = 1.f;
        P.ntiles = 3 * 256;
        gemm_bias_kernel<1><<<GRID_P, 128, SMEM_G128>>>(P);
    }
    // causal flash attention (fp16 out): 64-row q tiles
    attn_f16_kernel<<<dim3(NM / 64, NH, NB), 128, ASM_TOT>>>(hqh, hkh, hvh, ho);
    // output projection -> fp32 + bias (256 tiles < grid, effectively 1 wave)
    {
        GemmPtrs P{};
        P.A[0] = ho; P.W[0] = how; P.bias[0] = ob; P.Cf = out;
        P.ntiles = 256;
        gemm_bias_kernel<3><<<256, 128, SMEM_G128>>>(P);
    }
}

// round 17
// speedup vs baseline: 1.0180x; 1.0180x over previous
#include <cuda_runtime.h>
#include <cuda_fp16.h>
#include <math.h>
#include <stdint.h>

#define NB 2
#define NM 2048
#define ND 1024
#define NH 16
#define NHD 64
#define NTOK (NB*NM)   // 4096

// ---- fp16 scratch (static device globals: allocation-free) ----
__device__ __half h_x [NTOK*ND];
__device__ __half h_wq[ND*ND];
__device__ __half h_wk[ND*ND];
__device__ __half h_wv[ND*ND];
__device__ __half h_ipw[3*ND*ND];
__device__ __half h_ow[ND*ND];
__device__ __half h_q [NTOK*ND];
__device__ __half h_k [NTOK*ND];
__device__ __half h_v [NTOK*ND];
__device__ __half h_qh[NTOK*ND];
__device__ __half h_kh[NTOK*ND];
__device__ __half h_vh[NTOK*ND];
__device__ __half h_o [NTOK*ND];
__device__ float  g_theta[ND/2];

__global__ void init_theta_kernel() {
    int p = threadIdx.x;
    if (p < ND/2) {
        double e = -2.0 * ((double)p - 1.0) / (double)ND;
        g_theta[p] = (float)exp(e * log(10000.0));
    }
}

// ---- fused fp32 -> fp16 convert over 6 segments ----
struct CvtArgs {
    const float* src[6];
    __half*      dst[6];
    int          cum8[7];
};
__global__ void f2h_multi(CvtArgs a) {
    int i = blockIdx.x * blockDim.x + threadIdx.x;
    if (i >= a.cum8[6]) return;
    int s = 0;
#pragma unroll
    for (int t = 1; t < 6; t++) if (i >= a.cum8[t]) s = t;
    int j = i - a.cum8[s];
    const float4* in = (const float4*)a.src[s];
    uint2* out = (uint2*)a.dst[s];
    float4 x = in[2*j], y = in[2*j+1];
    __half2 h0 = __floats2half2_rn(x.x, x.y);
    __half2 h1 = __floats2half2_rn(x.z, x.w);
    __half2 h2 = __floats2half2_rn(y.x, y.y);
    __half2 h3 = __floats2half2_rn(y.z, y.w);
    out[2*j]   = make_uint2(*(uint32_t*)&h0, *(uint32_t*)&h1);
    out[2*j+1] = make_uint2(*(uint32_t*)&h2, *(uint32_t*)&h3);
}

// ---------------------------------------------------------------------------
// helpers
// ---------------------------------------------------------------------------
__device__ __forceinline__ uint32_t sptr(const void* p) {
    return (uint32_t)__cvta_generic_to_shared(p);
}
__device__ __forceinline__ void ldsm_x4(uint32_t* r, uint32_t a) {
    asm volatile("ldmatrix.sync.aligned.m8n8.x4.shared.b16 {%0,%1,%2,%3}, [%4];"
        : "=r"(r[0]), "=r"(r[1]), "=r"(r[2]), "=r"(r[3]) : "r"(a));
}
__device__ __forceinline__ void ldsm_x4t(uint32_t* r, uint32_t a) {
    asm volatile("ldmatrix.sync.aligned.m8n8.x4.trans.shared.b16 {%0,%1,%2,%3}, [%4];"
        : "=r"(r[0]), "=r"(r[1]), "=r"(r[2]), "=r"(r[3]) : "r"(a));
}
__device__ __forceinline__ void mma_f16(float* d, const uint32_t* a, uint32_t b0, uint32_t b1) {
    asm volatile(
        "mma.sync.aligned.m16n8k16.row.col.f32.f16.f16.f32 "
        "{%0,%1,%2,%3}, {%4,%5,%6,%7}, {%8,%9}, {%0,%1,%2,%3};"
        : "+f"(d[0]), "+f"(d[1]), "+f"(d[2]), "+f"(d[3])
        : "r"(a[0]), "r"(a[1]), "r"(a[2]), "r"(a[3]), "r"(b0), "r"(b1));
}
__device__ __forceinline__ void cp_async16(void* smem, const void* gmem) {
    asm volatile("cp.async.cg.shared.global [%0], [%1], 16;" :: "r"(sptr(smem)), "l"(gmem));
}
__device__ __forceinline__ void cp_commit() { asm volatile("cp.async.commit_group;"); }
template<int N> __device__ __forceinline__ void cp_wait() {
    asm volatile("cp.async.wait_group %0;" :: "n"(N));
}
__device__ __forceinline__ uint32_t packh2(float a, float b) {
    __half2 h = __floats2half2_rn(a, b);
    return *(uint32_t*)&h;
}

#define GLD 72          // padded smem row stride (halves)
#define NKB 16          // 1024 / 64

struct GemmPtrs {
    const __half* A[3];
    const __half* W[3];
    const float*  bias[3];
    __half*       Ch[3];
    float*        Cf;
    float         scale[3];
};

// ===========================================================================
// GEMM variant A (RoPE epilogue): 256 threads, 8 warps (64x32 tiles),
// BK=64, 2-stage. __launch_bounds__(256,2).  [R13 config]
// ===========================================================================
#define SMEM_G256 (4*128*GLD*2)   // 73728 bytes

__global__ __launch_bounds__(256, 2) void gemm_rope_kernel(GemmPtrs P)
{
    extern __shared__ __half smh[];
    __half* As = smh;                    // [2][128*GLD]
    __half* Bs = smh + 2 * 128 * GLD;

    const int tid  = threadIdx.x;
    const int lane = tid & 31, warp = tid >> 5;
    const int g = lane >> 2, tig = lane & 3;
    const int wm = (warp & 1) * 64, wn = (warp >> 1) * 32;
    const int sel = blockIdx.z;
    const int m0 = blockIdx.y << 7, n0 = blockIdx.x << 7;
    const __half* A = P.A[sel];
    const __half* W = P.W[sel];

    const int lrow = tid >> 3;
    const int lch  = (tid & 7) * 8;

    float acc[4][4][4];
#pragma unroll
    for (int mf = 0; mf < 4; mf++)
#pragma unroll
        for (int nf = 0; nf < 4; nf++)
#pragma unroll
            for (int t = 0; t < 4; t++) acc[mf][nf][t] = 0.f;

    auto issue = [&](int kb, int buf) {
        const __half* Ab = A + (size_t)m0 * ND + kb * 64 + lch;
        const __half* Wb = W + (size_t)n0 * ND + kb * 64 + lch;
        __half* Asb = As + buf * 128 * GLD;
        __half* Bsb = Bs + buf * 128 * GLD;
#pragma unroll
        for (int i = 0; i < 4; i++) {
            int r = lrow + i * 32;
            cp_async16(Asb + r * GLD + lch, Ab + (size_t)r * ND);
            cp_async16(Bsb + r * GLD + lch, Wb + (size_t)r * ND);
        }
    };

    const int a_row = lane & 15;
    const int a_col = (lane & 16) >> 1;

    issue(0, 0); cp_commit();
    int buf = 0;
#pragma unroll 1
    for (int kb = 0; kb < NKB; kb++) {
        if (kb + 1 < NKB) { issue(kb + 1, buf ^ 1); cp_commit(); cp_wait<1>(); }
        else              { cp_wait<0>(); }
        __syncthreads();

        const __half* Asb = As + buf * 128 * GLD;
        const __half* Bsb = Bs + buf * 128 * GLD;
#pragma unroll
        for (int s = 0; s < 4; s++) {
            uint32_t af[4][4];
#pragma unroll
            for (int mf = 0; mf < 4; mf++)
                ldsm_x4(af[mf], sptr(Asb + (wm + mf * 16 + a_row) * GLD + s * 16 + a_col));
            uint32_t bf[2][4];
#pragma unroll
            for (int np = 0; np < 2; np++) {
                int row = wn + np * 16 + (lane & 7) + ((lane & 16) >> 1);
                int col = s * 16 + (lane & 8);
                ldsm_x4(bf[np], sptr(Bsb + row * GLD + col));
            }
#pragma unroll
            for (int mf = 0; mf < 4; mf++)
#pragma unroll
                for (int np = 0; np < 2; np++) {
                    mma_f16(acc[mf][np * 2],     af[mf], bf[np][0], bf[np][1]);
                    mma_f16(acc[mf][np * 2 + 1], af[mf], bf[np][2], bf[np][3]);
                }
        }
        __syncthreads();
        buf ^= 1;
    }

    // RoPE epilogue (sincosf; c0/c1 = even/odd pair)
    __half* Ch = P.Ch[sel];
#pragma unroll
    for (int nf = 0; nf < 4; nf++) {
        int col = n0 + wn + nf * 8 + 2 * tig;
        float th = g_theta[col >> 1];
#pragma unroll
        for (int mf = 0; mf < 4; mf++) {
            int r0 = m0 + wm + mf * 16 + g;
#pragma unroll
            for (int hlf = 0; hlf < 2; hlf++) {
                int r = r0 + hlf * 8;
                float sn, cn;
                sincosf((float)(r & (NM - 1)) * th, &sn, &cn);
                float xe = acc[mf][nf][2 * hlf], xo = acc[mf][nf][2 * hlf + 1];
                *(__half2*)(Ch + (size_t)r * ND + col) =
                    __floats2half2_rn(xe * cn + xo * sn, -xe * sn + xo * cn);
            }
        }
    }
}

// ===========================================================================
// GEMM variant B (bias epilogues): 128 threads, 4 warps (64x64 tiles),
// BK=64, 3-stage, one sync/iter, fragment double-buffering.
// __launch_bounds__(128,2). EPI: 1 = (+bias)*scale -> fp16, 3 = +bias -> fp32.
// [R13 config]
// ===========================================================================
#define NSTG 3
#define STG_H (128*GLD)
#define SMEM_G128 (NSTG * 2 * STG_H * 2)   // 110592 bytes

template<int EPI>
__global__ __launch_bounds__(128, 2) void gemm_bias_kernel(GemmPtrs P)
{
    extern __shared__ __half smh[];
    const int tid  = threadIdx.x;
    const int lane = tid & 31, warp = tid >> 5;
    const int g = lane >> 2, tig = lane & 3;
    const int wm = (warp & 1) * 64, wn = (warp >> 1) * 64;
    const int sel = blockIdx.z;
    const int m0 = blockIdx.y << 7, n0 = blockIdx.x << 7;
    const __half* A = P.A[sel];
    const __half* W = P.W[sel];

    const int lrow = tid >> 3;           // 0..15
    const int lch  = (tid & 7) * 8;
    const int a_row = lane & 15;
    const int a_col = (lane & 16) >> 1;
    const int b_rsel = (lane & 7) + ((lane & 16) >> 1);
    const int b_csel = lane & 8;

    float acc[4][8][4];
#pragma unroll
    for (int mf = 0; mf < 4; mf++)
#pragma unroll
        for (int nf = 0; nf < 8; nf++)
#pragma unroll
            for (int t = 0; t < 4; t++) acc[mf][nf][t] = 0.f;

    auto issue = [&](int kb, int stg) {
        __half* Asb = smh + stg * 2 * STG_H;
        __half* Bsb = Asb + STG_H;
        const __half* Ap = A + (size_t)m0 * ND + kb * 64 + lch;
        const __half* Wp = W + (size_t)n0 * ND + kb * 64 + lch;
#pragma unroll
        for (int i = 0; i < 8; i++) {
            int r = lrow + i * 16;
            cp_async16(Asb + r * GLD + lch, Ap + (size_t)r * ND);
            cp_async16(Bsb + r * GLD + lch, Wp + (size_t)r * ND);
        }
    };

    issue(0, 0); cp_commit();
    issue(1, 1); cp_commit();

#pragma unroll 1
    for (int kb = 0; kb < NKB; kb++) {
        cp_wait<1>();
        __syncthreads();
        if (kb + 2 < NKB) issue(kb + 2, (kb + 2) % 3);
        cp_commit();

        const int stg = kb % 3;
        const __half* Asb = smh + stg * 2 * STG_H;
        const __half* Bsb = Asb + STG_H;

        uint32_t af[2][4][4], bf[2][4][4];
#pragma unroll
        for (int mf = 0; mf < 4; mf++)
            ldsm_x4(af[0][mf], sptr(Asb + (wm + mf * 16 + a_row) * GLD + a_col));
#pragma unroll
        for (int np = 0; np < 4; np++)
            ldsm_x4(bf[0][np], sptr(Bsb + (wn + np * 16 + b_rsel) * GLD + b_csel));

#pragma unroll
        for (int s = 0; s < 4; s++) {
            const int cur = s & 1, nxt = cur ^ 1;
            if (s < 3) {
#pragma unroll
                for (int mf = 0; mf < 4; mf++)
                    ldsm_x4(af[nxt][mf],
                        sptr(Asb + (wm + mf * 16 + a_row) * GLD + (s + 1) * 16 + a_col));
#pragma unroll
                for (int np = 0; np < 4; np++)
                    ldsm_x4(bf[nxt][np],
                        sptr(Bsb + (wn + np * 16 + b_rsel) * GLD + (s + 1) * 16 + b_csel));
            }
#pragma unroll
            for (int mf = 0; mf < 4; mf++)
#pragma unroll
                for (int np = 0; np < 4; np++) {
                    mma_f16(acc[mf][np * 2],     af[cur][mf], bf[cur][np][0], bf[cur][np][1]);
                    mma_f16(acc[mf][np * 2 + 1], af[cur][mf], bf[cur][np][2], bf[cur][np][3]);
                }
        }
    }

    if (EPI == 1) {
        float sc = P.scale[sel];
        __half* Ch = P.Ch[sel];
#pragma unroll
        for (int nf = 0; nf < 8; nf++) {
            int col = n0 + wn + nf * 8 + 2 * tig;
            float2 bv = *(const float2*)(P.bias[sel] + col);
#pragma unroll
            for (int mf = 0; mf < 4; mf++) {
                int r0 = m0 + wm + mf * 16 + g;
                *(__half2*)(Ch + (size_t)r0 * ND + col) =
                    __floats2half2_rn((acc[mf][nf][0] + bv.x) * sc,
                                      (acc[mf][nf][1] + bv.y) * sc);
                *(__half2*)(Ch + (size_t)(r0 + 8) * ND + col) =
                    __floats2half2_rn((acc[mf][nf][2] + bv.x) * sc,
                                      (acc[mf][nf][3] + bv.y) * sc);
            }
        }
    } else {
        float* Cf = P.Cf;
#pragma unroll
        for (int nf = 0; nf < 8; nf++) {
            int col = n0 + wn + nf * 8 + 2 * tig;
            float2 bv = *(const float2*)(P.bias[sel] + col);
#pragma unroll
            for (int mf = 0; mf < 4; mf++) {
                int r0 = m0 + wm + mf * 16 + g;
                float2 v0 = { acc[mf][nf][0] + bv.x, acc[mf][nf][1] + bv.y };
                float2 v1 = { acc[mf][nf][2] + bv.x, acc[mf][nf][3] + bv.y };
                *(float2*)(Cf + (size_t)r0 * ND + col)       = v0;
                *(float2*)(Cf + (size_t)(r0 + 8) * ND + col) = v1;
            }
        }
    }
}

// ===========================================================================
// Causal flash attention, fp16 mma.sync. Block = (64-q tile, h, b), 128 thr.
// 4 warps x 16 q rows. NEW: Q fragments hoisted to registers once;
// 3-buffer K/V ring -> ONE __syncthreads per key tile, 2-deep prefetch.
// P fed into P.V MMA directly from S registers. exp2 softmax.
// __launch_bounds__(128,3): smem 64512 B, regs <= 170.
// ===========================================================================
#define ATD 72
#define AKOFF (64*ATD)                 // Q: 64 rows, then 3 K bufs, 3 V bufs
#define AVOFF (AKOFF + 3*64*ATD)
#define ASM_TOT ((64 + 3*64 + 3*64) * ATD * 2)   // 64512 bytes

__global__ __launch_bounds__(128, 3) void attn_f16_kernel(
    const __half* __restrict__ qh, const __half* __restrict__ kh,
    const __half* __restrict__ vh, __half* __restrict__ o)
{
    extern __shared__ __half sm[];
    __half* Qs = sm;
    __half* Ks = sm + AKOFF;
    __half* Vs = sm + AVOFF;

    const int tid  = threadIdx.x;
    const int lane = tid & 31, warp = tid >> 5;
    const int g = lane >> 2, tig = lane & 3;
    const int qi = (int)gridDim.x - 1 - (int)blockIdx.x;   // longest first
    const int h = blockIdx.y, b = blockIdx.z;
    const int q0 = qi * 64;

    const __half* qb = qh + (size_t)b * NM * ND + h * NHD;
    const __half* kb = kh + (size_t)b * NM * ND + h * NHD;
    const __half* vb = vh + (size_t)b * NM * ND + h * NHD;

    const int lrow = tid >> 3;       // 0..15
    const int lch  = (tid & 7) * 8;
    const int a_row = lane & 15;
    const int a_col = (lane & 16) >> 1;

    // Group 0: Q tile (pre-scaled by 0.125*log2e upstream)
#pragma unroll
    for (int i = 0; i < 4; i++) {
        int r = lrow + i * 16;
        cp_async16(Qs + r * ATD + lch, qb + (size_t)(q0 + r) * ND + lch);
    }
    cp_commit();

    auto issue_kv = [&](int kt, int bufb) {
        int k0 = kt * 64;
        __half* Kd = Ks + bufb * 64 * ATD;
        __half* Vd = Vs + bufb * 64 * ATD;
#pragma unroll
        for (int i = 0; i < 4; i++) {
            int r = lrow + i * 16;
            cp_async16(Kd + r * ATD + lch, kb + (size_t)(k0 + r) * ND + lch);
            cp_async16(Vd + r * ATD + lch, vb + (size_t)(k0 + r) * ND + lch);
        }
    };

    // Groups 1,2: kv0, kv1 (kv1 may be empty)
    issue_kv(0, 0); cp_commit();
    if (qi >= 1) issue_kv(1, 1);
    cp_commit();

    // Hoist Q fragments (wait for group 0; 2 newer kv groups outstanding)
    cp_wait<2>();
    __syncthreads();
    uint32_t qf[4][4];
#pragma unroll
    for (int s = 0; s < 4; s++)
        ldsm_x4(qf[s], sptr(Qs + (warp * 16 + a_row) * ATD + s * 16 + a_col));

    float m_i[2] = { -INFINITY, -INFINITY };
    float l_i[2] = { 0.f, 0.f };
    float Oa[8][4];
#pragma unroll
    for (int nf = 0; nf < 8; nf++)
#pragma unroll
        for (int t = 0; t < 4; t++) Oa[nf][t] = 0.f;

    for (int kt = 0; kt <= qi; kt++) {
        cp_wait<1>();            // kv_kt landed ({kv_kt, kv_kt+1} were outstanding)
        __syncthreads();         // also orders prior reads of buffer (kt)%3 rewrite
        if (kt + 2 <= qi) issue_kv(kt + 2, (kt + 2) % 3);
        cp_commit();             // one group per iteration (possibly empty)

        const __half* Kb = Ks + (kt % 3) * 64 * ATD;
        const __half* Vb = Vs + (kt % 3) * 64 * ATD;

        // S = Q K^T  (m16 x n64 x k64 per warp), Q from registers
        float S[8][4];
#pragma unroll
        for (int nf = 0; nf < 8; nf++)
#pragma unroll
            for (int t = 0; t < 4; t++) S[nf][t] = 0.f;

#pragma unroll
        for (int s = 0; s < 4; s++) {
#pragma unroll
            for (int np = 0; np < 4; np++) {
                uint32_t bf[4];
                int row = np * 16 + (lane & 7) + ((lane & 16) >> 1);
                int col = s * 16 + (lane & 8);
                ldsm_x4(bf, sptr(Kb + row * ATD + col));
                mma_f16(S[np * 2],     qf[s], bf[0], bf[1]);
                mma_f16(S[np * 2 + 1], qf[s], bf[2], bf[3]);
            }
        }

        if (kt == qi) {   // diagonal tile: causal mask (local coords)
            const int r0 = warp * 16 + g, r1 = r0 + 8;
#pragma unroll
            for (int nf = 0; nf < 8; nf++) {
                int c = nf * 8 + 2 * tig;
                if (c     > r0) S[nf][0] = -INFINITY;
                if (c + 1 > r0) S[nf][1] = -INFINITY;
                if (c     > r1) S[nf][2] = -INFINITY;
                if (c + 1 > r1) S[nf][3] = -INFINITY;
            }
        }

        // online softmax in log2 domain (rows g, g+8; 4 lanes/row -> xor 1,2)
#pragma unroll
        for (int r = 0; r < 2; r++) {
            float mx = -INFINITY;
#pragma unroll
            for (int nf = 0; nf < 8; nf++)
                mx = fmaxf(mx, fmaxf(S[nf][2 * r], S[nf][2 * r + 1]));
            mx = fmaxf(mx, __shfl_xor_sync(0xffffffffu, mx, 1));
            mx = fmaxf(mx, __shfl_xor_sync(0xffffffffu, mx, 2));
            float mn = fmaxf(m_i[r], mx);
            float alpha = exp2f(m_i[r] - mn);
            float rs = 0.f;
#pragma unroll
            for (int nf = 0; nf < 8; nf++) {
                float p0 = exp2f(S[nf][2 * r] - mn);
                float p1 = exp2f(S[nf][2 * r + 1] - mn);
                S[nf][2 * r] = p0; S[nf][2 * r + 1] = p1;
                rs += p0 + p1;
            }
            rs += __shfl_xor_sync(0xffffffffu, rs, 1);
            rs += __shfl_xor_sync(0xffffffffu, rs, 2);
            l_i[r] = l_i[r] * alpha + rs;
            m_i[r] = mn;
#pragma unroll
            for (int nf = 0; nf < 8; nf++) {
                Oa[nf][2 * r]     *= alpha;
                Oa[nf][2 * r + 1] *= alpha;
            }
        }

        // O += P V : P A-fragments packed directly from S registers
#pragma unroll
        for (int s = 0; s < 4; s++) {
            uint32_t af[4];
            af[0] = packh2(S[2 * s][0],     S[2 * s][1]);
            af[1] = packh2(S[2 * s][2],     S[2 * s][3]);
            af[2] = packh2(S[2 * s + 1][0], S[2 * s + 1][1]);
            af[3] = packh2(S[2 * s + 1][2], S[2 * s + 1][3]);
#pragma unroll
            for (int np = 0; np < 4; np++) {
                uint32_t bf[4];
                int row = s * 16 + (lane & 7) + (lane & 8);
                int col = np * 16 + ((lane & 16) >> 1);
                ldsm_x4t(bf, sptr(Vb + row * ATD + col));
                mma_f16(Oa[np * 2],     af, bf[0], bf[1]);
                mma_f16(Oa[np * 2 + 1], af, bf[2], bf[3]);
            }
        }
    }

    __half* ob = o + (size_t)b * NM * ND + h * NHD;
#pragma unroll
    for (int r = 0; r < 2; r++) {
        float inv = 1.f / l_i[r];
        int row = q0 + warp * 16 + g + r * 8;
#pragma unroll
        for (int nf = 0; nf < 8; nf++)
            *(__half2*)(ob + (size_t)row * ND + nf * 8 + 2 * tig) =
                __floats2half2_rn(Oa[nf][2 * r] * inv, Oa[nf][2 * r + 1] * inv);
    }
}

// ===========================================================================
extern "C" void kernel_launch(void* const* d_in, const int* in_sizes, int n_in,
                              void* d_out, int out_size)
{
    const float* x   = (const float*)d_in[0];
    const float* wq  = (const float*)d_in[1];
    const float* wk  = (const float*)d_in[2];
    const float* wv  = (const float*)d_in[3];
    const float* ipw = (const float*)d_in[4];
    const float* ipb = (const float*)d_in[5];
    const float* ow  = (const float*)d_in[6];
    const float* ob  = (const float*)d_in[7];
    float* out = (float*)d_out;

    __half *hx, *hwq, *hwk, *hwv, *hipw, *how, *hq, *hk, *hv, *hqh, *hkh, *hvh, *ho;
    cudaGetSymbolAddress((void**)&hx,  h_x);
    cudaGetSymbolAddress((void**)&hwq, h_wq);
    cudaGetSymbolAddress((void**)&hwk, h_wk);
    cudaGetSymbolAddress((void**)&hwv, h_wv);
    cudaGetSymbolAddress((void**)&hipw, h_ipw);
    cudaGetSymbolAddress((void**)&how, h_ow);
    cudaGetSymbolAddress((void**)&hq,  h_q);
    cudaGetSymbolAddress((void**)&hk,  h_k);
    cudaGetSymbolAddress((void**)&hv,  h_v);
    cudaGetSymbolAddress((void**)&hqh, h_qh);
    cudaGetSymbolAddress((void**)&hkh, h_kh);
    cudaGetSymbolAddress((void**)&hvh, h_vh);
    cudaGetSymbolAddress((void**)&ho,  h_o);

    cudaFuncSetAttribute(gemm_rope_kernel,
                         cudaFuncAttributeMaxDynamicSharedMemorySize, SMEM_G256);
    cudaFuncSetAttribute(gemm_bias_kernel<1>,
                         cudaFuncAttributeMaxDynamicSharedMemorySize, SMEM_G128);
    cudaFuncSetAttribute(gemm_bias_kernel<3>,
                         cudaFuncAttributeMaxDynamicSharedMemorySize, SMEM_G128);
    cudaFuncSetAttribute(attn_f16_kernel,
                         cudaFuncAttributeMaxDynamicSharedMemorySize, ASM_TOT);

    init_theta_kernel<<<1, 512>>>();

    // fused converts
    {
        CvtArgs a{};
        const float* srcs[6] = { x, wq, wk, wv, ipw, ow };
        __half* dsts[6] = { hx, hwq, hwk, hwv, hipw, how };
        int sizes[6] = { NTOK*ND, ND*ND, ND*ND, ND*ND, 3*ND*ND, ND*ND };
        int cum = 0;
        for (int i = 0; i < 6; i++) {
            a.src[i] = srcs[i]; a.dst[i] = dsts[i];
            a.cum8[i] = cum; cum += sizes[i] / 8;
        }
        a.cum8[6] = cum;
        f2h_multi<<<(cum + 255) / 256, 256>>>(a);
    }

    // QKV projections with fused RoPE epilogue (fp16 out), 256-thread kernel
    {
        GemmPtrs P{};
        P.A[0] = hx; P.A[1] = hx; P.A[2] = hx;
        P.W[0] = hwq; P.W[1] = hwk; P.W[2] = hwv;
        P.Ch[0] = hq; P.Ch[1] = hk; P.Ch[2] = hv;
        gemm_rope_kernel<<<dim3(8, 32, 3), 256, SMEM_G256>>>(P);
    }
    // in_proj (bias fused; qh scaled by 0.125*log2e) - 128-thread frag-pipelined
    {
        GemmPtrs P{};
        P.A[0] = hq; P.A[1] = hk; P.A[2] = hv;
        P.W[0] = hipw; P.W[1] = hipw + ND * ND; P.W[2] = hipw + 2 * ND * ND;
        P.bias[0] = ipb; P.bias[1] = ipb + ND; P.bias[2] = ipb + 2 * ND;
        P.Ch[0] = hqh; P.Ch[1] = hkh; P.Ch[2] = hvh;
        P.scale[0] = 0.125f * 1.44269504088896341f; P.scale[1] = 1.f; P.scale[2] = 1.f;
        gemm_bias_kernel<1><<<dim3(8, 32, 3), 128, SMEM_G128>>>(P);
    }
    // causal flash attention (fp16 out): 64-row q tiles
    attn_f16_kernel<<<dim3(NM / 64, NH, NB), 128, ASM_TOT>>>(hqh, hkh, hvh, ho);
    // output projection -> fp32 + bias
    {
        GemmPtrs P{};
        P.A[0] = ho; P.W[0] = how; P.bias[0] = ob; P.Cf = out;
        gemm_bias_kernel<3><<<dim3(8, 32, 1), 128, SMEM_G128>>>(P);
    }
}